// round 13
// baseline (speedup 1.0000x reference)
#include <cuda_runtime.h>
#include <cstdint>
#include <cstddef>

constexpr int H = 4096, Bn = 32, G4 = 16384;     // hidden, batch, 4H
constexpr int BH = Bn * H;                       // 131072
constexpr int LAYER_W = G4 * H;                  // weight elems per layer-matrix
constexpr int CH = 4;                            // k16-steps per chunk (64 K floats)
constexpr int NCHP = 64;                         // chunks per weight matrix (4096/64)
constexpr int NCH = 2 * NCHP;                    // 128 chunks (ih pass + hh pass)

// ---- smem stage layout (bytes) ----
constexpr int A_STRIDE_B = 272;                  // 256B data + 16B pad (68 floats)
constexpr int A_BYTES = 128 * A_STRIDE_B;        // 34816
constexpr int B_OFF   = A_BYTES;
constexpr int B_NSTR  = 5;                       // uint4 per B row (4 data + 1 pad)
constexpr int B_BYTES = CH * 32 * B_NSTR * 16;   // 10240
constexpr int STAGE   = A_BYTES + B_BYTES;       // 45056
constexpr int NSTAGE  = 4;
constexpr int SMEM_TOTAL = NSTAGE * STAGE;       // 180224

// ---- scratch (device globals; no allocation) ----
// frag layout per layer: index ((c*32 + n)*4 + t4), c = k16 step 0..255
__device__ uint4 g_xfrag[2][256 * 32 * 4];       // input-act frags per layer
__device__ uint4 g_hfrag[2][256 * 32 * 4];       // hidden-act frags per layer

// ---- helpers ----
__device__ __forceinline__ uint32_t smem_u32(const void* p) {
    uint32_t r;
    asm("{ .reg .u64 t; cvta.to.shared.u64 t, %1; cvt.u32.u64 %0, t; }" : "=r"(r) : "l"(p));
    return r;
}

// split float2 -> (hi bf16x2 = truncation, lo bf16x2 = rn(residual))
__device__ __forceinline__ void split2(float2 p, uint32_t& h, uint32_t& l) {
    uint32_t u0 = __float_as_uint(p.x), u1 = __float_as_uint(p.y);
    h = __byte_perm(u0, u1, 0x7632);
    float l0 = p.x - __uint_as_float(u0 & 0xFFFF0000u);
    float l1 = p.y - __uint_as_float(u1 & 0xFFFF0000u);
    asm("cvt.rn.bf16x2.f32 %0, %1, %2;" : "=r"(l) : "f"(l1), "f"(l0));
}

__device__ __forceinline__ void mma16816(float* d, const uint32_t* a, uint32_t b0, uint32_t b1) {
    asm volatile(
        "mma.sync.aligned.m16n8k16.row.col.f32.bf16.bf16.f32 "
        "{%0,%1,%2,%3}, {%4,%5,%6,%7}, {%8,%9}, {%0,%1,%2,%3};\n"
        : "+f"(d[0]), "+f"(d[1]), "+f"(d[2]), "+f"(d[3])
        : "r"(a[0]), "r"(a[1]), "r"(a[2]), "r"(a[3]), "r"(b0), "r"(b1));
}

#define CP_ASYNC16(smaddr, gptr) \
    asm volatile("cp.async.cg.shared.global [%0], [%1], 16;" :: "r"(smaddr), "l"(gptr) : "memory")
#define CP_COMMIT()  asm volatile("cp.async.commit_group;" ::: "memory")
#define CP_WAIT2()   asm volatile("cp.async.wait_group 2;" ::: "memory")
#define CP_WAIT1()   asm volatile("cp.async.wait_group 1;" ::: "memory")
#define CP_WAIT0()   asm volatile("cp.async.wait_group 0;" ::: "memory")

// ---- prep: fp32 activations -> frag-ordered bf16 hi/lo (3 tensors) ----
__global__ void prep_kernel(const float* __restrict__ x, const float* __restrict__ h) {
    int idx = blockIdx.x * blockDim.x + threadIdx.x;     // 0..98303
    int i2 = idx & 32767;
    const float* s;
    uint4* d;
    if (idx < 32768)      { s = x;        d = g_xfrag[0]; }
    else if (idx < 65536) { s = h;        d = g_hfrag[0]; }
    else                  { s = h + BH;   d = g_hfrag[1]; }
    int t4 = i2 & 3, n = (i2 >> 2) & 31, c = i2 >> 7;
    int k0 = c * 16 + 2 * t4;
    float2 p0 = *(const float2*)&s[(size_t)n * H + k0];
    float2 p1 = *(const float2*)&s[(size_t)n * H + k0 + 8];
    uint4 v;
    split2(p0, v.x, v.z);
    split2(p1, v.y, v.w);
    d[i2] = v;
}

// ---- GEMM + fused LSTM cell ----
// grid 128 CTAs x 256 thr. CTA owns h-rows [h0,h0+32) of ALL 4 gate blocks.
// warp w: gate = w>>1, rows j0 = gate*H + h0 + (w&1)*16 (+0..15), cols n=0..31.
__global__ void __launch_bounds__(256, 1) gemm_kernel(
    const float* __restrict__ Wih, const float* __restrict__ Whh,
    const float* __restrict__ bih, const float* __restrict__ bhh,
    const uint4* __restrict__ Fx, const uint4* __restrict__ Fh,
    const float* __restrict__ prev_c, float* __restrict__ out,
    uint4* __restrict__ Fdst, int layer)
{
    extern __shared__ char smem[];
    const int tid = threadIdx.x, lane = tid & 31, wid = tid >> 5;
    const int g = lane >> 2, t4 = lane & 3;
    const int h0 = blockIdx.x * 32;
    const uint32_t sm0 = smem_u32(smem);

    float acc[4][4] = {};

    // stage chunk ch (0..127) into buffer ch&3
    auto stage = [&](int ch) {
        const int pass = ch >> 6, cc = ch & 63;
        const float* W = pass ? Whh : Wih;
        const uint4* F = pass ? Fh : Fx;
        const uint32_t sb = sm0 + (uint32_t)(ch & 3) * STAGE;
        // A: 128 rows x 256B = 2048 x 16B segs
        #pragma unroll
        for (int i = 0; i < 8; ++i) {
            int s = tid + i * 256;
            int r = s >> 4, seg = s & 15;
            int j = (r >> 5) * H + h0 + ((r >> 4) & 1) * 16 + (r & 15);
            const float* gp = W + (size_t)j * H + cc * 64 + seg * 4;
            const void* gg = (const void*)__cvta_generic_to_global((void*)gp);
            CP_ASYNC16(sb + (uint32_t)r * A_STRIDE_B + (uint32_t)seg * 16u, gg);
        }
        // B: 512 x 16B frags, scatter into padded rows
        #pragma unroll
        for (int i = 0; i < 2; ++i) {
            int s = tid + i * 256;
            int kk = s >> 7, n = (s >> 2) & 31, tt = s & 3;
            const void* gg = (const void*)__cvta_generic_to_global((void*)(F + (size_t)cc * 512 + s));
            CP_ASYNC16(sb + B_OFF + (uint32_t)((kk * 32 + n) * B_NSTR + tt) * 16u, gg);
        }
        CP_COMMIT();
    };

    stage(0); stage(1); stage(2);

    #pragma unroll 1
    for (int ch = 0; ch < NCH; ++ch) {
        if (ch < NCH - 2)       { CP_WAIT2(); }
        else if (ch == NCH - 2) { CP_WAIT1(); }
        else                    { CP_WAIT0(); }
        __syncthreads();
        if (ch + 3 < NCH) stage(ch + 3);     // issue loads BEFORE compute

        const char* sb = smem + (size_t)(ch & 3) * STAGE;
        const float* rowA0 = (const float*)(sb + (size_t)(wid * 16 + g) * A_STRIDE_B);
        const float* rowA1 = (const float*)(sb + (size_t)(wid * 16 + g + 8) * A_STRIDE_B);
        const uint4* sBp = (const uint4*)(sb + B_OFF);

        #pragma unroll
        for (int kk = 0; kk < CH; ++kk) {
            const int col = kk * 16 + 2 * t4;
            float2 a0 = *(const float2*)(rowA0 + col);
            float2 a1 = *(const float2*)(rowA1 + col);
            float2 a2 = *(const float2*)(rowA0 + col + 8);
            float2 a3 = *(const float2*)(rowA1 + col + 8);
            uint32_t ah[4], al[4];
            split2(a0, ah[0], al[0]);
            split2(a1, ah[1], al[1]);
            split2(a2, ah[2], al[2]);
            split2(a3, ah[3], al[3]);

            uint4 bb[4];
            #pragma unroll
            for (int t = 0; t < 4; ++t)
                bb[t] = sBp[(kk * 32 + 8 * t + g) * B_NSTR + t4];   // {bh0,bh1,bl0,bl1}

            #pragma unroll
            for (int t = 0; t < 4; ++t) mma16816(acc[t], ah, bb[t].x, bb[t].y);  // Ah*Bh
            #pragma unroll
            for (int t = 0; t < 4; ++t) mma16816(acc[t], ah, bb[t].z, bb[t].w);  // Ah*Bl
            #pragma unroll
            for (int t = 0; t < 4; ++t) mma16816(acc[t], al, bb[t].x, bb[t].y);  // Al*Bh
        }
    }

    // ---- fused epilogue: exchange gates via smem, apply LSTM cell ----
    float* ex  = (float*)smem;                       // [4 gates][32 hh][33] (padded)
    float* hnt = (float*)smem + 4 * 32 * 33;         // [32 hh][33]  (layer-0 hn tile)

    const int gate = wid >> 1;
    const int hh0 = (wid & 1) * 16;
    const int j0 = gate * H + h0 + hh0;
    const float biA = bih[j0 + g] + bhh[j0 + g];
    const float biB = bih[j0 + g + 8] + bhh[j0 + g + 8];
    #pragma unroll
    for (int t = 0; t < 4; ++t) {
        const int n = 8 * t + 2 * t4;
        float* e0 = &ex[((gate * 32) + hh0 + g) * 33 + n];
        e0[0] = acc[t][0] + biA;  e0[1] = acc[t][1] + biA;
        float* e1 = &ex[((gate * 32) + hh0 + g + 8) * 33 + n];
        e1[0] = acc[t][2] + biB;  e1[1] = acc[t][3] + biB;
    }
    __syncthreads();

    #pragma unroll
    for (int i = 0; i < 4; ++i) {
        const int p = tid + i * 256;                 // 1024 (b,hh) pairs
        const int b = p >> 5, hh = p & 31;
        const float gi = ex[(0 * 32 + hh) * 33 + b];
        const float gf = ex[(1 * 32 + hh) * 33 + b];
        const float gg = ex[(2 * 32 + hh) * 33 + b];
        const float go = ex[(3 * 32 + hh) * 33 + b];
        const float si = 1.f / (1.f + expf(-gi));
        const float sf = 1.f / (1.f + expf(-gf));
        const float so = 1.f / (1.f + expf(-go));
        const float c  = prev_c[(size_t)b * H + h0 + hh];
        const float cn = sf * c + si * tanhf(gg);
        const float hn = so * tanhf(cn);
        out[(size_t)layer * BH + (size_t)b * H + h0 + hh]       = hn;  // next_h
        out[(size_t)(2 + layer) * BH + (size_t)b * H + h0 + hh] = cn;  // next_c
        if (layer == 0) hnt[hh * 33 + b] = hn;
    }

    // layer 0: emit layer-1 input B-fragments for this CTA's 32 h-values
    if (layer == 0) {
        __syncthreads();
        const int q = tid;                           // 256 frags: 2 c x 32 n x 4 t4
        const int cl = q >> 7, n = (q >> 2) & 31, tq = q & 3;
        const int kl = cl * 16 + 2 * tq;
        float2 p0 = make_float2(hnt[kl * 33 + n],       hnt[(kl + 1) * 33 + n]);
        float2 p1 = make_float2(hnt[(kl + 8) * 33 + n], hnt[(kl + 9) * 33 + n]);
        uint4 v;
        split2(p0, v.x, v.z);
        split2(p1, v.y, v.w);
        Fdst[(size_t)((h0 / 16 + cl) * 32 + n) * 4 + tq] = v;
    }
}

// ---- launch ----
extern "C" void kernel_launch(void* const* d_in, const int* in_sizes, int n_in,
                              void* d_out, int out_size) {
    const float* inputs = (const float*)d_in[0];
    const float* prev_h = (const float*)d_in[1];
    const float* prev_c = (const float*)d_in[2];
    const float* W_ih   = (const float*)d_in[3];
    const float* W_hh   = (const float*)d_in[4];
    const float* b_ih   = (const float*)d_in[5];
    const float* b_hh   = (const float*)d_in[6];
    float* out = (float*)d_out;

    cudaFuncSetAttribute(gemm_kernel,
                         cudaFuncAttributeMaxDynamicSharedMemorySize, SMEM_TOTAL);

    uint4 *fx0, *fx1, *fh0, *fh1;
    cudaGetSymbolAddress((void**)&fx0, g_xfrag);
    fx1 = fx0 + 256 * 32 * 4;
    cudaGetSymbolAddress((void**)&fh0, g_hfrag);
    fh1 = fh0 + 256 * 32 * 4;

    prep_kernel<<<384, 256>>>(inputs, prev_h);
    gemm_kernel<<<128, 256, SMEM_TOTAL>>>(W_ih, W_hh, b_ih, b_hh,
                                          fx0, fh0, prev_c, out, fx1, 0);
    gemm_kernel<<<128, 256, SMEM_TOTAL>>>(W_ih + (size_t)LAYER_W, W_hh + (size_t)LAYER_W,
                                          b_ih + G4, b_hh + G4,
                                          fx1, fh1, prev_c + BH, out, nullptr, 1);
}

// round 14
// speedup vs baseline: 1.4445x; 1.4445x over previous
#include <cuda_runtime.h>
#include <cstdint>
#include <cstddef>

constexpr int H = 4096, B = 32, G4 = 16384;      // hidden, batch, 4H
constexpr int BH = B * H;                        // 131072
constexpr int LAYER_W = G4 * H;                  // weight elems per layer-matrix
constexpr int KSTEPS = H / 16;                   // 256 k16 steps per matrix
constexpr int CH = 8;                            // ksteps per smem chunk (128 floats of K)
constexpr int NCHP = KSTEPS / CH;                // 32 chunks per pass
constexpr int NCH = 2 * NCHP;                    // 64 chunks total (ih pass + hh pass)

// ---- smem layout (bytes, per stage) ---- (m64 tile)
constexpr int A_STRIDE_F = 132;                  // 128 + 4 pad floats
constexpr int A_STRIDE_B = A_STRIDE_F * 4;       // 528
constexpr int A_BYTES = 64 * A_STRIDE_B;         // 33792
constexpr int B_OFF   = A_BYTES;
constexpr int B_BYTES = CH * 32 * 4 * 16;        // 16384
constexpr int STAGE   = A_BYTES + B_BYTES;       // 50176
constexpr int SMEM_TOTAL = 2 * STAGE;            // 100352  (2 CTAs/SM)

// ---- scratch (device globals; no allocation) ----
__device__ float g_gates[(size_t)G4 * B];        // 2 MB
__device__ uint4 g_xfrag[2][KSTEPS * B * 4];     // input-act frags per layer (512 KB ea)
__device__ uint4 g_hfrag[2][KSTEPS * B * 4];     // hidden-act frags per layer
__device__ float g_hnew[BH];                     // layer-0 h_new (fp32)

// ---- helpers ----
__device__ __forceinline__ uint32_t smem_u32(const void* p) {
    uint32_t r;
    asm("{ .reg .u64 t; cvta.to.shared.u64 t, %1; cvt.u32.u64 %0, t; }" : "=r"(r) : "l"(p));
    return r;
}

// split float2 -> (hi bf16x2 = truncation, lo bf16x2 = rn(residual))
__device__ __forceinline__ void split2(float2 p, uint32_t& h, uint32_t& l) {
    uint32_t u0 = __float_as_uint(p.x), u1 = __float_as_uint(p.y);
    h = __byte_perm(u0, u1, 0x7632);
    float l0 = p.x - __uint_as_float(u0 & 0xFFFF0000u);
    float l1 = p.y - __uint_as_float(u1 & 0xFFFF0000u);
    asm("cvt.rn.bf16x2.f32 %0, %1, %2;" : "=r"(l) : "f"(l1), "f"(l0));
}

__device__ __forceinline__ void mma16816(float* d, const uint32_t* a, uint32_t b0, uint32_t b1) {
    asm volatile(
        "mma.sync.aligned.m16n8k16.row.col.f32.bf16.bf16.f32 "
        "{%0,%1,%2,%3}, {%4,%5,%6,%7}, {%8,%9}, {%0,%1,%2,%3};\n"
        : "+f"(d[0]), "+f"(d[1]), "+f"(d[2]), "+f"(d[3])
        : "r"(a[0]), "r"(a[1]), "r"(a[2]), "r"(a[3]), "r"(b0), "r"(b1));
}

#define CP_ASYNC16(smaddr, gptr) \
    asm volatile("cp.async.cg.shared.global [%0], [%1], 16;" :: "r"(smaddr), "l"(gptr) : "memory")
#define CP_COMMIT()  asm volatile("cp.async.commit_group;" ::: "memory")
#define CP_WAIT1()   asm volatile("cp.async.wait_group 1;" ::: "memory")
#define CP_WAIT0()   asm volatile("cp.async.wait_group 0;" ::: "memory")

// ---- prep: fp32 activations -> frag-ordered bf16 hi/lo ----
// covers xfrag[0] (inputs), hfrag[0] (prev_h[0]), hfrag[1] (prev_h[1])
__global__ void prep3_kernel(const float* __restrict__ x, const float* __restrict__ h) {
    int idx = blockIdx.x * blockDim.x + threadIdx.x;        // 0..98303
    int i2 = idx & 32767;
    const float* s;
    uint4* d;
    if (idx < 32768)      { s = x;      d = g_xfrag[0]; }
    else if (idx < 65536) { s = h;      d = g_hfrag[0]; }
    else                  { s = h + BH; d = g_hfrag[1]; }
    int t4 = i2 & 3, n = (i2 >> 2) & 31, c = i2 >> 7;
    int k0 = c * 16 + 2 * t4;
    float2 p0 = *(const float2*)&s[(size_t)n * H + k0];
    float2 p1 = *(const float2*)&s[(size_t)n * H + k0 + 8];
    uint4 v;
    split2(p0, v.x, v.z);
    split2(p1, v.y, v.w);
    d[i2] = v;
}

// g_hnew -> g_xfrag[1]
__global__ void prep1_kernel() {
    int i2 = blockIdx.x * blockDim.x + threadIdx.x;         // 0..32767
    int t4 = i2 & 3, n = (i2 >> 2) & 31, c = i2 >> 7;
    int k0 = c * 16 + 2 * t4;
    float2 p0 = *(const float2*)&g_hnew[(size_t)n * H + k0];
    float2 p1 = *(const float2*)&g_hnew[(size_t)n * H + k0 + 8];
    uint4 v;
    split2(p0, v.x, v.z);
    split2(p1, v.y, v.w);
    g_xfrag[1][i2] = v;
}

// ---- GEMM: gates = Wih@x^T + Whh@h^T + bih + bhh ----
// grid=256 CTAs, 128 threads (4 warps), 2 CTAs/SM. CTA owns 64 contiguous gate
// rows; warp w owns rows m_base + w*16. Double-buffered cp.async over 64 chunks.
__global__ void __launch_bounds__(128, 2) gemm_kernel(
    const float* __restrict__ Wih, const float* __restrict__ Whh,
    const float* __restrict__ bih, const float* __restrict__ bhh,
    const uint4* __restrict__ Fx, const uint4* __restrict__ Fh)
{
    extern __shared__ char smem[];
    const int tid = threadIdx.x, lane = tid & 31, wid = tid >> 5;
    const int g = lane >> 2, t4 = lane & 3;
    const int m_base = blockIdx.x * 64;
    const int m0 = m_base + wid * 16;                 // warp's 16 rows
    const uint32_t sm0 = smem_u32(smem);

    float acc[4][4] = {};                             // 4 n-tiles x 4 f32

    // stage chunk ch (0..63) into buffer (ch&1)
    auto stage = [&](int ch) {
        const int pass = ch >> 5, cc = ch & 31;
        const float* W = pass ? Whh : Wih;
        const uint4* F = pass ? Fh : Fx;
        const uint32_t sb = sm0 + (uint32_t)(ch & 1) * STAGE;
        // A: 64 rows x 512B, as 2048 x 16B segments
        #pragma unroll
        for (int i = 0; i < 16; ++i) {
            int s = tid + i * 128;
            int row = s >> 5, seg = s & 31;
            const float* gp = W + (size_t)(m_base + row) * H + cc * 128 + seg * 4;
            const void* gg = (const void*)__cvta_generic_to_global((void*)gp);
            CP_ASYNC16(sb + (uint32_t)row * A_STRIDE_B + (uint32_t)seg * 16u, gg);
        }
        // B: 1024 x 16B frags
        #pragma unroll
        for (int i = 0; i < 8; ++i) {
            int s = tid + i * 128;
            const void* gg = (const void*)__cvta_generic_to_global((void*)(F + (size_t)cc * 1024 + s));
            CP_ASYNC16(sb + B_OFF + (uint32_t)s * 16u, gg);
        }
        CP_COMMIT();
    };

    stage(0);
    stage(1);

    #pragma unroll 1
    for (int ch = 0; ch < NCH; ++ch) {
        if (ch + 1 < NCH) { CP_WAIT1(); } else { CP_WAIT0(); }
        __syncthreads();

        const char* sb = smem + (ch & 1) * STAGE;
        const char* rowA0 = sb + (size_t)(wid * 16 + g) * A_STRIDE_B;        // row g
        const char* rowA1 = rowA0 + 8 * A_STRIDE_B;                          // row g+8
        const uint4* sB = (const uint4*)(sb + B_OFF);

        #pragma unroll
        for (int kk = 0; kk < CH; ++kk) {
            const int col = kk * 16 + 2 * t4;
            float2 a0 = *(const float2*)(rowA0 + col * 4);
            float2 a1 = *(const float2*)(rowA1 + col * 4);
            float2 a2 = *(const float2*)(rowA0 + (col + 8) * 4);
            float2 a3 = *(const float2*)(rowA1 + (col + 8) * 4);
            uint32_t ah[4], al[4];
            split2(a0, ah[0], al[0]);
            split2(a1, ah[1], al[1]);
            split2(a2, ah[2], al[2]);
            split2(a3, ah[3], al[3]);

            uint4 bb[4];
            #pragma unroll
            for (int t = 0; t < 4; ++t)
                bb[t] = sB[kk * 128 + (8 * t + g) * 4 + t4];   // {bh0,bh1,bl0,bl1}

            // term-outer order: consecutive MMAs hit independent acc[t] chains
            #pragma unroll
            for (int t = 0; t < 4; ++t) mma16816(acc[t], ah, bb[t].x, bb[t].y);  // Ah*Bh
            #pragma unroll
            for (int t = 0; t < 4; ++t) mma16816(acc[t], ah, bb[t].z, bb[t].w);  // Ah*Bl
            #pragma unroll
            for (int t = 0; t < 4; ++t) mma16816(acc[t], al, bb[t].x, bb[t].y);  // Al*Bh
        }
        __syncthreads();
        if (ch + 2 < NCH) stage(ch + 2);
    }

    // epilogue: add biases, write gates[j][b] (j-major, batch contiguous)
    const int j0 = m0 + g;
    const float bi0 = bih[j0] + bhh[j0];
    const float bi1 = bih[j0 + 8] + bhh[j0 + 8];
    #pragma unroll
    for (int t = 0; t < 4; ++t) {
        int colb = 8 * t + 2 * t4;
        *(float2*)&g_gates[(size_t)j0 * B + colb] =
            make_float2(acc[t][0] + bi0, acc[t][1] + bi0);
        *(float2*)&g_gates[(size_t)(j0 + 8) * B + colb] =
            make_float2(acc[t][2] + bi1, acc[t][3] + bi1);
    }
}

// ---- LSTM cell (elementwise) ----
__global__ void cell_kernel(const float* __restrict__ prev_c, float* __restrict__ out, int l) {
    int idx = blockIdx.x * blockDim.x + threadIdx.x;         // b*H + h
    int h = idx & (H - 1), b = idx >> 12;
    float gi = g_gates[(size_t)h * B + b];
    float gf = g_gates[(size_t)(H + h) * B + b];
    float gg = g_gates[(size_t)(2 * H + h) * B + b];
    float go = g_gates[(size_t)(3 * H + h) * B + b];
    float si = 1.f / (1.f + expf(-gi));
    float sf = 1.f / (1.f + expf(-gf));
    float so = 1.f / (1.f + expf(-go));
    float c = prev_c[(size_t)l * BH + idx];
    float cn = sf * c + si * tanhf(gg);
    float hn = so * tanhf(cn);
    out[(size_t)(0 * 2 + l) * BH + idx] = hn;                // next_h
    out[(size_t)(1 * 2 + l) * BH + idx] = cn;                // next_c
    if (l == 0) g_hnew[idx] = hn;                            // feeds layer 1
}

// ---- launch ----
extern "C" void kernel_launch(void* const* d_in, const int* in_sizes, int n_in,
                              void* d_out, int out_size) {
    const float* inputs = (const float*)d_in[0];
    const float* prev_h = (const float*)d_in[1];
    const float* prev_c = (const float*)d_in[2];
    const float* W_ih   = (const float*)d_in[3];
    const float* W_hh   = (const float*)d_in[4];
    const float* b_ih   = (const float*)d_in[5];
    const float* b_hh   = (const float*)d_in[6];
    float* out = (float*)d_out;

    cudaFuncSetAttribute(gemm_kernel,
                         cudaFuncAttributeMaxDynamicSharedMemorySize, SMEM_TOTAL);

    uint4 *fx0, *fh0;
    cudaGetSymbolAddress((void**)&fx0, g_xfrag);
    cudaGetSymbolAddress((void**)&fh0, g_hfrag);
    uint4* fx1 = fx0 + KSTEPS * B * 4;
    uint4* fh1 = fh0 + KSTEPS * B * 4;

    // layer 0
    prep3_kernel<<<384, 256>>>(inputs, prev_h);
    gemm_kernel<<<256, 128, SMEM_TOTAL>>>(W_ih, W_hh, b_ih, b_hh, fx0, fh0);
    cell_kernel<<<512, 256>>>(prev_c, out, 0);
    // layer 1
    prep1_kernel<<<128, 256>>>();
    gemm_kernel<<<256, 128, SMEM_TOTAL>>>(W_ih + (size_t)LAYER_W, W_hh + (size_t)LAYER_W,
                                          b_ih + G4, b_hh + G4, fx1, fh1);
    cell_kernel<<<512, 256>>>(prev_c, out, 1);
}